// round 7
// baseline (speedup 1.0000x reference)
#include <cuda_runtime.h>
#include <math.h>

#define NN 50000
#define EE 800000
#define ET (NN + EE)          // 850000 edges incl. self loops
#define NCH 98                // ceil(NN / 512)

// ---------------- scratch (device globals; no allocation allowed) ----------
__device__ float g_h1[(size_t)NN * 256];   // x @ W1
__device__ float g_h [(size_t)NN * 256];   // elu(gat1 out)
__device__ float g_h2[(size_t)NN * 64];    // h @ W2
__device__ float g_t [(size_t)NN * 64];    // decoder hidden
__device__ float g_as1[NN * 4];
__device__ float g_ad1[NN * 4];
__device__ float g_as2[NN];
__device__ float g_ad2[NN];
__device__ int   g_deg[NN];
__device__ int   g_off[NN + 1];
__device__ int   g_cur[NN];
__device__ int   g_srcid[ET];
__device__ int   g_csum[NCH];
__device__ int   g_ei64;

__device__ __forceinline__ float lrelu(float v) { return v >= 0.f ? v : 0.2f * v; }

__device__ __forceinline__ int load_edge(const int* __restrict__ ei, int j) {
    return g_ei64 ? ei[(size_t)j * 2] : ei[j];   // little-endian low word
}

__global__ void k_flag(float* __restrict__ z, float v) { z[0] = v; }

__global__ void k_zero_out(float* __restrict__ o, int n) {
    int i = blockIdx.x * blockDim.x + threadIdx.x;
    if (i < n) o[i] = 0.f;
}

// ---------------- init: zero degrees + dtype detect -------------------------
__global__ void k_init(const int* __restrict__ ei) {
    int i = blockIdx.x * blockDim.x + threadIdx.x;
    if (i < NN) g_deg[i] = 0;
    if (i == 0) {
        int odd_nz = 0, even_nz = 0;
        for (int j = 0; j < 256; j += 2) {
            if (ei[j]     != 0) even_nz++;
            if (ei[j + 1] != 0) odd_nz++;
        }
        g_ei64 = (odd_nz == 0 && even_nz > 0) ? 1 : 0;
    }
}

// ---------------- CSR build -------------------------------------------------
__global__ void k_count(const int* __restrict__ ei) {
    int e = blockIdx.x * blockDim.x + threadIdx.x;
    if (e >= ET) return;
    int dst = (e < EE) ? load_edge(ei, EE + e) : (e - EE);
    if ((unsigned)dst < (unsigned)NN) atomicAdd(&g_deg[dst], 1);
}

__global__ void k_scan_chunk() {
    __shared__ int s[512];
    int tid = threadIdx.x;
    int i = blockIdx.x * 512 + tid;
    int v = (i < NN) ? g_deg[i] : 0;
    s[tid] = v;
    __syncthreads();
    for (int o = 1; o < 512; o <<= 1) {
        int t = (tid >= o) ? s[tid - o] : 0;
        __syncthreads();
        s[tid] += t;
        __syncthreads();
    }
    if (i < NN) g_off[i] = s[tid] - v;
    if (tid == 511) g_csum[blockIdx.x] = s[511];
}

__global__ void k_scan_mid() {
    if (threadIdx.x == 0 && blockIdx.x == 0) {
        int acc = 0;
        for (int i = 0; i < NCH; i++) { int v = g_csum[i]; g_csum[i] = acc; acc += v; }
    }
}

__global__ void k_scan_add() {
    int i = blockIdx.x * 512 + threadIdx.x;
    if (i < NN) {
        int o = g_off[i] + g_csum[blockIdx.x];
        g_off[i] = o;
        g_cur[i] = o;
    }
    if (i == 0) g_off[NN] = ET;
}

__global__ void k_scatter(const int* __restrict__ ei) {
    int e = blockIdx.x * blockDim.x + threadIdx.x;
    if (e >= ET) return;
    int s, d;
    if (e < EE) { s = load_edge(ei, e); d = load_edge(ei, EE + e); }
    else        { s = d = e - EE; }
    if ((unsigned)d >= (unsigned)NN || (unsigned)s >= (unsigned)NN) return;
    int p = atomicAdd(&g_cur[d], 1);
    if ((unsigned)p < (unsigned)ET) g_srcid[p] = s;
}

// ------- GEMM A: BM=128, BN=128, BK=16, 256 thr, 8x8 micro (for GEMM1) -----
__global__ void k_gemm128(const float* __restrict__ A, const float* __restrict__ B,
                          float* __restrict__ C, int M, int K, int Nc) {
    __shared__ float As[16][132];
    __shared__ float Bs[16][132];
    int bm = blockIdx.y * 128, bn = blockIdx.x * 128;
    int tid = threadIdx.x;
    int tx = tid & 15, ty = tid >> 4;
    float acc[8][8] = {};
    for (int k0 = 0; k0 < K; k0 += 16) {
        #pragma unroll
        for (int t = 0; t < 2; t++) {
            int i = (tid + t * 256) * 4;
            int r = i >> 4, c = i & 15;
            int gr = bm + r;
            float4 v = (gr < M) ? *(const float4*)&A[(size_t)gr * K + k0 + c]
                                : make_float4(0.f, 0.f, 0.f, 0.f);
            As[c + 0][r] = v.x; As[c + 1][r] = v.y; As[c + 2][r] = v.z; As[c + 3][r] = v.w;
        }
        #pragma unroll
        for (int t = 0; t < 2; t++) {
            int i = (tid + t * 256) * 4;
            int r = i >> 7, c = i & 127;
            *(float4*)&Bs[r][c] = *(const float4*)&B[(size_t)(k0 + r) * Nc + bn + c];
        }
        __syncthreads();
        #pragma unroll
        for (int k = 0; k < 16; k++) {
            float a[8], b[8];
            *(float4*)&a[0] = *(float4*)&As[k][ty * 8];
            *(float4*)&a[4] = *(float4*)&As[k][ty * 8 + 4];
            *(float4*)&b[0] = *(float4*)&Bs[k][tx * 8];
            *(float4*)&b[4] = *(float4*)&Bs[k][tx * 8 + 4];
            #pragma unroll
            for (int u = 0; u < 8; u++)
                #pragma unroll
                for (int v = 0; v < 8; v++) acc[u][v] += a[u] * b[v];
        }
        __syncthreads();
    }
    #pragma unroll
    for (int u = 0; u < 8; u++) {
        int gr = bm + ty * 8 + u;
        if (gr < M) {
            *(float4*)&C[(size_t)gr * Nc + bn + tx * 8]     =
                make_float4(acc[u][0], acc[u][1], acc[u][2], acc[u][3]);
            *(float4*)&C[(size_t)gr * Nc + bn + tx * 8 + 4] =
                make_float4(acc[u][4], acc[u][5], acc[u][6], acc[u][7]);
        }
    }
}

// ------- GEMM B: BM=128, BN=64, BK=16, 256 thr, 8x4; epi: 0 none,1 bias,2 bias+elu
__global__ void k_gemm64(const float* __restrict__ A, const float* __restrict__ B,
                         float* __restrict__ C, int M, int K, int Nc,
                         const float* __restrict__ bias, int epi) {
    __shared__ float As[16][132];
    __shared__ float Bs[16][68];
    int bm = blockIdx.y * 128, bn = blockIdx.x * 64;
    int tid = threadIdx.x;
    int tx = tid & 15, ty = tid >> 4;
    float acc[8][4] = {};
    for (int k0 = 0; k0 < K; k0 += 16) {
        #pragma unroll
        for (int i = tid; i < 128 * 16; i += 256) {
            int r = i >> 4, c = i & 15;
            int gr = bm + r;
            As[c][r] = (gr < M) ? A[(size_t)gr * K + k0 + c] : 0.f;
        }
        #pragma unroll
        for (int i = tid; i < 16 * 64; i += 256) {
            int r = i >> 6, c = i & 63;
            Bs[r][c] = B[(size_t)(k0 + r) * Nc + bn + c];
        }
        __syncthreads();
        #pragma unroll
        for (int k = 0; k < 16; k++) {
            float a[8], b[4];
            #pragma unroll
            for (int u = 0; u < 8; u++) a[u] = As[k][ty * 8 + u];
            #pragma unroll
            for (int v = 0; v < 4; v++) b[v] = Bs[k][tx * 4 + v];
            #pragma unroll
            for (int u = 0; u < 8; u++)
                #pragma unroll
                for (int v = 0; v < 4; v++) acc[u][v] += a[u] * b[v];
        }
        __syncthreads();
    }
    float bb[4] = {0.f, 0.f, 0.f, 0.f};
    if (epi) {
        #pragma unroll
        for (int v = 0; v < 4; v++) bb[v] = bias[bn + tx * 4 + v];
    }
    #pragma unroll
    for (int u = 0; u < 8; u++) {
        int gr = bm + ty * 8 + u;
        if (gr < M) {
            float o[4];
            #pragma unroll
            for (int v = 0; v < 4; v++) {
                float t = acc[u][v] + bb[v];
                if (epi == 2) t = t > 0.f ? t : __expf(t) - 1.f;
                o[v] = t;
            }
            *(float4*)&C[(size_t)gr * Nc + bn + tx * 4] = make_float4(o[0], o[1], o[2], o[3]);
        }
    }
}

// ---------------- attention coefficients (layer 1) --------------------------
__global__ void k_att1(const float* __restrict__ att_s, const float* __restrict__ att_d) {
    int w = (blockIdx.x * blockDim.x + threadIdx.x) >> 5;
    int lane = threadIdx.x & 31;
    if (w >= NN) return;
    int c = lane * 8;
    const float4* hp = (const float4*)&g_h1[(size_t)w * 256 + c];
    float4 h0 = hp[0], h1 = hp[1];
    const float4* sp = (const float4*)&att_s[c];
    const float4* dp = (const float4*)&att_d[c];
    float4 s0 = sp[0], s1 = sp[1], d0 = dp[0], d1 = dp[1];
    float ps = h0.x * s0.x + h0.y * s0.y + h0.z * s0.z + h0.w * s0.w
             + h1.x * s1.x + h1.y * s1.y + h1.z * s1.z + h1.w * s1.w;
    float pd = h0.x * d0.x + h0.y * d0.y + h0.z * d0.z + h0.w * d0.w
             + h1.x * d1.x + h1.y * d1.y + h1.z * d1.z + h1.w * d1.w;
    #pragma unroll
    for (int o = 1; o < 8; o <<= 1) {
        ps += __shfl_xor_sync(0xffffffffu, ps, o);
        pd += __shfl_xor_sync(0xffffffffu, pd, o);
    }
    if ((lane & 7) == 0) {
        int h = lane >> 3;
        g_as1[w * 4 + h] = ps;
        g_ad1[w * 4 + h] = pd;
    }
}

// ---- fused GAT layer-1 aggregation (warp/node, single pass, unroll x2) ----
__global__ void k_agg1(const float* __restrict__ b1) {
    int node = (blockIdx.x * blockDim.x + threadIdx.x) >> 5;
    int lane = threadIdx.x & 31;
    if (node >= NN) return;
    int beg = g_off[node], end = g_off[node + 1];
    int hh = lane >> 3;
    float adh = g_ad1[node * 4 + hh];

    float a0=0,a1=0,a2=0,a3=0,a4=0,a5=0,a6=0,a7=0;
    float den = 0.f;
    int i = beg;
    for (; i + 2 <= end; i += 2) {
        int s0 = g_srcid[i], s1 = g_srcid[i + 1];
        float w0 = __expf(lrelu(g_as1[s0 * 4 + hh] + adh));
        float w1 = __expf(lrelu(g_as1[s1 * 4 + hh] + adh));
        const float4* p0 = (const float4*)&g_h1[(size_t)s0 * 256 + lane * 8];
        const float4* p1 = (const float4*)&g_h1[(size_t)s1 * 256 + lane * 8];
        float4 ha0 = p0[0], hb0 = p0[1];
        float4 ha1 = p1[0], hb1 = p1[1];
        den += w0 + w1;
        a0 += ha0.x * w0 + ha1.x * w1; a1 += ha0.y * w0 + ha1.y * w1;
        a2 += ha0.z * w0 + ha1.z * w1; a3 += ha0.w * w0 + ha1.w * w1;
        a4 += hb0.x * w0 + hb1.x * w1; a5 += hb0.y * w0 + hb1.y * w1;
        a6 += hb0.z * w0 + hb1.z * w1; a7 += hb0.w * w0 + hb1.w * w1;
    }
    if (i < end) {
        int s = g_srcid[i];
        float w = __expf(lrelu(g_as1[s * 4 + hh] + adh));
        den += w;
        const float4* hp = (const float4*)&g_h1[(size_t)s * 256 + lane * 8];
        float4 ha = hp[0], hb = hp[1];
        a0 += ha.x * w; a1 += ha.y * w; a2 += ha.z * w; a3 += ha.w * w;
        a4 += hb.x * w; a5 += hb.y * w; a6 += hb.z * w; a7 += hb.w * w;
    }
    float inv = 1.f / (den + 1e-16f);
    const float4* bp = (const float4*)&b1[lane * 8];
    float4 bb0 = bp[0], bb1 = bp[1];
    float o0 = a0*inv+bb0.x, o1 = a1*inv+bb0.y, o2 = a2*inv+bb0.z, o3 = a3*inv+bb0.w;
    float o4 = a4*inv+bb1.x, o5 = a5*inv+bb1.y, o6 = a6*inv+bb1.z, o7 = a7*inv+bb1.w;
    o0 = o0 > 0.f ? o0 : __expf(o0) - 1.f; o1 = o1 > 0.f ? o1 : __expf(o1) - 1.f;
    o2 = o2 > 0.f ? o2 : __expf(o2) - 1.f; o3 = o3 > 0.f ? o3 : __expf(o3) - 1.f;
    o4 = o4 > 0.f ? o4 : __expf(o4) - 1.f; o5 = o5 > 0.f ? o5 : __expf(o5) - 1.f;
    o6 = o6 > 0.f ? o6 : __expf(o6) - 1.f; o7 = o7 > 0.f ? o7 : __expf(o7) - 1.f;
    float4* op = (float4*)&g_h[(size_t)node * 256 + lane * 8];
    op[0] = make_float4(o0, o1, o2, o3);
    op[1] = make_float4(o4, o5, o6, o7);
}

// ---------------- attention coefficients (layer 2, 1 head) -----------------
__global__ void k_att2(const float* __restrict__ att_s, const float* __restrict__ att_d) {
    int w = (blockIdx.x * blockDim.x + threadIdx.x) >> 5;
    int lane = threadIdx.x & 31;
    if (w >= NN) return;
    float2 h = *(const float2*)&g_h2[(size_t)w * 64 + lane * 2];
    float2 as = *(const float2*)&att_s[lane * 2];
    float2 ad = *(const float2*)&att_d[lane * 2];
    float ps = h.x * as.x + h.y * as.y;
    float pd = h.x * ad.x + h.y * ad.y;
    #pragma unroll
    for (int o = 16; o > 0; o >>= 1) {
        ps += __shfl_xor_sync(0xffffffffu, ps, o);
        pd += __shfl_xor_sync(0xffffffffu, pd, o);
    }
    if (lane == 0) { g_as2[w] = ps; g_ad2[w] = pd; }
}

// ---- fused GAT layer-2 aggregation + L2 normalize (single pass) -----------
__global__ void k_agg2(const float* __restrict__ b2, float* __restrict__ zout) {
    int node = (blockIdx.x * blockDim.x + threadIdx.x) >> 5;
    int lane = threadIdx.x & 31;
    if (node >= NN) return;
    int beg = g_off[node], end = g_off[node + 1];
    float ad = g_ad2[node];

    float acc0 = 0.f, acc1 = 0.f, den = 0.f;
    int i = beg;
    for (; i + 2 <= end; i += 2) {
        int s0 = g_srcid[i], s1 = g_srcid[i + 1];
        float w0 = __expf(lrelu(g_as2[s0] + ad));
        float w1 = __expf(lrelu(g_as2[s1] + ad));
        float2 h0 = *(const float2*)&g_h2[(size_t)s0 * 64 + lane * 2];
        float2 h1 = *(const float2*)&g_h2[(size_t)s1 * 64 + lane * 2];
        den += w0 + w1;
        acc0 += h0.x * w0 + h1.x * w1;
        acc1 += h0.y * w0 + h1.y * w1;
    }
    if (i < end) {
        int s = g_srcid[i];
        float w = __expf(lrelu(g_as2[s] + ad));
        den += w;
        float2 h = *(const float2*)&g_h2[(size_t)s * 64 + lane * 2];
        acc0 += h.x * w; acc1 += h.y * w;
    }
    float inv = 1.f / (den + 1e-16f);
    float2 bb = *(const float2*)&b2[lane * 2];
    float z0 = acc0 * inv + bb.x;
    float z1 = acc1 * inv + bb.y;
    float ss = z0 * z0 + z1 * z1;
    #pragma unroll
    for (int o = 16; o > 0; o >>= 1)
        ss += __shfl_xor_sync(0xffffffffu, ss, o);
    float invn = 1.f / fmaxf(sqrtf(ss), 1e-12f);
    float2* zp = (float2*)&zout[(size_t)node * 64 + lane * 2];
    *zp = make_float2(z0 * invn, z1 * invn);
}

// ---------------- launcher ---------------------------------------------------
extern "C" void kernel_launch(void* const* d_in, const int* in_sizes, int n_in,
                              void* d_out, int out_size) {
    float* z = (float*)d_out;                       // [NN,64]
    float* xhat = (out_size >= 9600000) ? (z + (size_t)NN * 64) : 0;

    if (out_size != 9600000)
        k_zero_out<<<(out_size + 511) / 512, 512>>>((float*)d_out, out_size);

    // real device addresses of scratch globals
    float *p_h1 = 0, *p_h = 0, *p_h2 = 0, *p_t = 0;
    cudaGetSymbolAddress((void**)&p_h1, g_h1);
    cudaGetSymbolAddress((void**)&p_h,  g_h);
    cudaGetSymbolAddress((void**)&p_h2, g_h2);
    cudaGetSymbolAddress((void**)&p_t,  g_t);

    // side stream + events for CSR/GEMM overlap (created once)
    static cudaStream_t s1 = 0;
    static cudaEvent_t evFork = 0, evJoin = 0;
    if (!s1) {
        cudaStreamCreateWithFlags(&s1, cudaStreamNonBlocking);
        cudaEventCreateWithFlags(&evFork, cudaEventDisableTiming);
        cudaEventCreateWithFlags(&evJoin, cudaEventDisableTiming);
    }

    // ---- input resolution: positional (dict order) verified by sizes ----
    static const int expect[14] = {6400000, 1600000, 32768, 256, 256, 256,
                                   16384, 64, 64, 64, 4096, 64, 8192, 128};
    bool positionalOK = (n_in == 14);
    if (positionalOK) {
        for (int i = 0; i < 14; i++) {
            int s = in_sizes[i];
            if (s != expect[i] && !(i == 1 && s == 3200000)) { positionalOK = false; break; }
        }
    }

    const float *x = 0, *W1 = 0, *W2 = 0, *dW1 = 0, *dW2 = 0, *db2 = 0;
    const float *atts1 = 0, *attd1 = 0, *b1 = 0, *atts2 = 0, *attd2 = 0, *b2 = 0, *db1 = 0;
    const int* ei = 0;

    if (positionalOK) {
        x     = (const float*)d_in[0];
        ei    = (const int*)  d_in[1];
        W1    = (const float*)d_in[2];
        atts1 = (const float*)d_in[3];
        attd1 = (const float*)d_in[4];
        b1    = (const float*)d_in[5];
        W2    = (const float*)d_in[6];
        atts2 = (const float*)d_in[7];
        attd2 = (const float*)d_in[8];
        b2    = (const float*)d_in[9];
        dW1   = (const float*)d_in[10];
        db1   = (const float*)d_in[11];
        dW2   = (const float*)d_in[12];
        db2   = (const float*)d_in[13];
    } else {
        const float* g256[3] = {0, 0, 0};
        const float* g64[4]  = {0, 0, 0, 0};
        int n256 = 0, n64 = 0;
        for (int i = 0; i < n_in; i++) {
            int s = in_sizes[i];
            const float* p = (const float*)d_in[i];
            if      (s == 6400000) x   = p;
            else if (s == 1600000 || s == 3200000) ei = (const int*)d_in[i];
            else if (s == 32768)   W1  = p;
            else if (s == 16384)   W2  = p;
            else if (s == 4096)    dW1 = p;
            else if (s == 8192)    dW2 = p;
            else if (s == 128)     db2 = p;
            else if (s == 256 && n256 < 3) g256[n256++] = p;
            else if (s == 64  && n64  < 4) g64[n64++]   = p;
        }
        bool dictLike = (n_in > 0 && in_sizes[0] == 6400000);
        atts1 = g256[dictLike ? 0 : 1];
        attd1 = g256[dictLike ? 1 : 0];
        b1    = g256[2];
        atts2 = g64[dictLike ? 0 : 1];
        attd2 = g64[dictLike ? 1 : 0];
        b2    = g64[2];
        db1   = g64[3];
        if (!x || !ei || !W1 || !W2 || !dW1 || !dW2 || !db2 || n256 < 3 || n64 < 4) {
            k_flag<<<1, 1>>>(z, 1e12f);
            return;
        }
    }

    // ---- fork: CSR build on side stream, overlapped with GEMM1/att1 ----
    cudaEventRecord(evFork, 0);
    cudaStreamWaitEvent(s1, evFork, 0);

    k_init   <<<(NN + 255) / 256, 256, 0, s1>>>(ei);
    k_count  <<<(ET + 255) / 256, 256, 0, s1>>>(ei);
    k_scan_chunk<<<NCH, 512, 0, s1>>>();
    k_scan_mid  <<<1, 32, 0, s1>>>();
    k_scan_add  <<<NCH, 512, 0, s1>>>();
    k_scatter<<<(ET + 255) / 256, 256, 0, s1>>>(ei);
    cudaEventRecord(evJoin, s1);

    // ---- main stream: layer-1 feature path ----
    {
        dim3 g(2, (NN + 127) / 128);
        k_gemm128<<<g, 256>>>(x, W1, p_h1, NN, 128, 256);
    }
    k_att1<<<(NN * 32 + 255) / 256, 256>>>(atts1, attd1);

    // join CSR before aggregation
    cudaStreamWaitEvent(0, evJoin, 0);
    k_agg1<<<(NN * 32 + 255) / 256, 256>>>(b1);

    // ---- layer 2 ----
    {
        dim3 g(1, (NN + 127) / 128);
        k_gemm64<<<g, 256>>>(p_h, W2, p_h2, NN, 256, 64, (const float*)0, 0);
    }
    k_att2<<<(NN * 32 + 255) / 256, 256>>>(atts2, attd2);
    k_agg2<<<(NN * 32 + 255) / 256, 256>>>(b2, z);

    // ---- decoder as two GEMMs ----
    if (xhat) {
        dim3 g1(1, (NN + 127) / 128);
        k_gemm64<<<g1, 256>>>(z, dW1, p_t, NN, 64, 64, db1, 2);     // elu(z@dW1+db1)
        dim3 g2(2, (NN + 127) / 128);
        k_gemm64<<<g2, 256>>>(p_t, dW2, xhat, NN, 64, 128, db2, 1); // @dW2+db2
    }
}

// round 8
// speedup vs baseline: 1.5099x; 1.5099x over previous
#include <cuda_runtime.h>
#include <cuda_fp16.h>
#include <math.h>

#define NN 50000
#define EE 800000
#define ET (NN + EE)          // 850000 edges incl. self loops
#define NCH 98                // ceil(NN / 512)

// ---------------- scratch (device globals; no allocation allowed) ----------
__device__ float   g_h1[(size_t)NN * 256];   // x @ W1 (fp32)
__device__ __half2 g_h1h[(size_t)NN * 128];  // fp16 copy for edge gather
__device__ float   g_h [(size_t)NN * 256];   // elu(gat1 out)
__device__ float   g_h2[(size_t)NN * 64];    // h @ W2
__device__ __half2 g_h2h[(size_t)NN * 32];   // fp16 copy for edge gather
__device__ float   g_t [(size_t)NN * 64];    // decoder hidden
__device__ float g_as1[NN * 4];
__device__ float g_ad1[NN * 4];
__device__ float g_as2[NN];
__device__ float g_ad2[NN];
__device__ int   g_deg[NN];
__device__ int   g_off[NN + 1];
__device__ int   g_cur[NN];
__device__ int   g_srcid[ET];
__device__ int   g_csum[NCH];
__device__ int   g_ei64;

__device__ __forceinline__ float lrelu(float v) { return v >= 0.f ? v : 0.2f * v; }

__device__ __forceinline__ int load_edge(const int* __restrict__ ei, int j) {
    return g_ei64 ? ei[(size_t)j * 2] : ei[j];   // little-endian low word
}

__global__ void k_flag(float* __restrict__ z, float v) { z[0] = v; }

__global__ void k_zero_out(float* __restrict__ o, int n) {
    int i = blockIdx.x * blockDim.x + threadIdx.x;
    if (i < n) o[i] = 0.f;
}

// ---------------- init: zero degrees + dtype detect -------------------------
__global__ void k_init(const int* __restrict__ ei) {
    int i = blockIdx.x * blockDim.x + threadIdx.x;
    if (i < NN) g_deg[i] = 0;
    if (i == 0) {
        int odd_nz = 0, even_nz = 0;
        for (int j = 0; j < 256; j += 2) {
            if (ei[j]     != 0) even_nz++;
            if (ei[j + 1] != 0) odd_nz++;
        }
        g_ei64 = (odd_nz == 0 && even_nz > 0) ? 1 : 0;
    }
}

// ---------------- CSR build -------------------------------------------------
__global__ void k_count(const int* __restrict__ ei) {
    int e = blockIdx.x * blockDim.x + threadIdx.x;
    if (e >= ET) return;
    int dst = (e < EE) ? load_edge(ei, EE + e) : (e - EE);
    if ((unsigned)dst < (unsigned)NN) atomicAdd(&g_deg[dst], 1);
}

__global__ void k_scan_chunk() {
    __shared__ int s[512];
    int tid = threadIdx.x;
    int i = blockIdx.x * 512 + tid;
    int v = (i < NN) ? g_deg[i] : 0;
    s[tid] = v;
    __syncthreads();
    for (int o = 1; o < 512; o <<= 1) {
        int t = (tid >= o) ? s[tid - o] : 0;
        __syncthreads();
        s[tid] += t;
        __syncthreads();
    }
    if (i < NN) g_off[i] = s[tid] - v;
    if (tid == 511) g_csum[blockIdx.x] = s[511];
}

__global__ void k_scan_mid() {
    if (threadIdx.x == 0 && blockIdx.x == 0) {
        int acc = 0;
        for (int i = 0; i < NCH; i++) { int v = g_csum[i]; g_csum[i] = acc; acc += v; }
    }
}

__global__ void k_scan_add() {
    int i = blockIdx.x * 512 + threadIdx.x;
    if (i < NN) {
        int o = g_off[i] + g_csum[blockIdx.x];
        g_off[i] = o;
        g_cur[i] = o;
    }
    if (i == 0) g_off[NN] = ET;
}

__global__ void k_scatter(const int* __restrict__ ei) {
    int e = blockIdx.x * blockDim.x + threadIdx.x;
    if (e >= ET) return;
    int s, d;
    if (e < EE) { s = load_edge(ei, e); d = load_edge(ei, EE + e); }
    else        { s = d = e - EE; }
    if ((unsigned)d >= (unsigned)NN || (unsigned)s >= (unsigned)NN) return;
    int p = atomicAdd(&g_cur[d], 1);
    if ((unsigned)p < (unsigned)ET) g_srcid[p] = s;
}

// ------- GEMM A: BM=128, BN=128, BK=16, 256 thr, 8x8 micro (for GEMM1) -----
__global__ void k_gemm128(const float* __restrict__ A, const float* __restrict__ B,
                          float* __restrict__ C, int M, int K, int Nc) {
    __shared__ float As[16][132];
    __shared__ float Bs[16][132];
    int bm = blockIdx.y * 128, bn = blockIdx.x * 128;
    int tid = threadIdx.x;
    int tx = tid & 15, ty = tid >> 4;
    float acc[8][8] = {};
    for (int k0 = 0; k0 < K; k0 += 16) {
        #pragma unroll
        for (int t = 0; t < 2; t++) {
            int i = (tid + t * 256) * 4;
            int r = i >> 4, c = i & 15;
            int gr = bm + r;
            float4 v = (gr < M) ? *(const float4*)&A[(size_t)gr * K + k0 + c]
                                : make_float4(0.f, 0.f, 0.f, 0.f);
            As[c + 0][r] = v.x; As[c + 1][r] = v.y; As[c + 2][r] = v.z; As[c + 3][r] = v.w;
        }
        #pragma unroll
        for (int t = 0; t < 2; t++) {
            int i = (tid + t * 256) * 4;
            int r = i >> 7, c = i & 127;
            *(float4*)&Bs[r][c] = *(const float4*)&B[(size_t)(k0 + r) * Nc + bn + c];
        }
        __syncthreads();
        #pragma unroll
        for (int k = 0; k < 16; k++) {
            float a[8], b[8];
            *(float4*)&a[0] = *(float4*)&As[k][ty * 8];
            *(float4*)&a[4] = *(float4*)&As[k][ty * 8 + 4];
            *(float4*)&b[0] = *(float4*)&Bs[k][tx * 8];
            *(float4*)&b[4] = *(float4*)&Bs[k][tx * 8 + 4];
            #pragma unroll
            for (int u = 0; u < 8; u++)
                #pragma unroll
                for (int v = 0; v < 8; v++) acc[u][v] += a[u] * b[v];
        }
        __syncthreads();
    }
    #pragma unroll
    for (int u = 0; u < 8; u++) {
        int gr = bm + ty * 8 + u;
        if (gr < M) {
            *(float4*)&C[(size_t)gr * Nc + bn + tx * 8]     =
                make_float4(acc[u][0], acc[u][1], acc[u][2], acc[u][3]);
            *(float4*)&C[(size_t)gr * Nc + bn + tx * 8 + 4] =
                make_float4(acc[u][4], acc[u][5], acc[u][6], acc[u][7]);
        }
    }
}

// ------- GEMM B: BM=128, BN=64, BK=16, 256 thr, 8x4; epi: 0 none,1 bias,2 bias+elu
__global__ void k_gemm64(const float* __restrict__ A, const float* __restrict__ B,
                         float* __restrict__ C, int M, int K, int Nc,
                         const float* __restrict__ bias, int epi) {
    __shared__ float As[16][132];
    __shared__ float Bs[16][68];
    int bm = blockIdx.y * 128, bn = blockIdx.x * 64;
    int tid = threadIdx.x;
    int tx = tid & 15, ty = tid >> 4;
    float acc[8][4] = {};
    for (int k0 = 0; k0 < K; k0 += 16) {
        #pragma unroll
        for (int i = tid; i < 128 * 16; i += 256) {
            int r = i >> 4, c = i & 15;
            int gr = bm + r;
            As[c][r] = (gr < M) ? A[(size_t)gr * K + k0 + c] : 0.f;
        }
        #pragma unroll
        for (int i = tid; i < 16 * 64; i += 256) {
            int r = i >> 6, c = i & 63;
            Bs[r][c] = B[(size_t)(k0 + r) * Nc + bn + c];
        }
        __syncthreads();
        #pragma unroll
        for (int k = 0; k < 16; k++) {
            float a[8], b[4];
            #pragma unroll
            for (int u = 0; u < 8; u++) a[u] = As[k][ty * 8 + u];
            #pragma unroll
            for (int v = 0; v < 4; v++) b[v] = Bs[k][tx * 4 + v];
            #pragma unroll
            for (int u = 0; u < 8; u++)
                #pragma unroll
                for (int v = 0; v < 4; v++) acc[u][v] += a[u] * b[v];
        }
        __syncthreads();
    }
    float bb[4] = {0.f, 0.f, 0.f, 0.f};
    if (epi) {
        #pragma unroll
        for (int v = 0; v < 4; v++) bb[v] = bias[bn + tx * 4 + v];
    }
    #pragma unroll
    for (int u = 0; u < 8; u++) {
        int gr = bm + ty * 8 + u;
        if (gr < M) {
            float o[4];
            #pragma unroll
            for (int v = 0; v < 4; v++) {
                float t = acc[u][v] + bb[v];
                if (epi == 2) t = t > 0.f ? t : __expf(t) - 1.f;
                o[v] = t;
            }
            *(float4*)&C[(size_t)gr * Nc + bn + tx * 4] = make_float4(o[0], o[1], o[2], o[3]);
        }
    }
}

// ---- attention coefficients (layer 1) + fp16 copy of h1 -------------------
__global__ void k_att1(const float* __restrict__ att_s, const float* __restrict__ att_d) {
    int w = (blockIdx.x * blockDim.x + threadIdx.x) >> 5;
    int lane = threadIdx.x & 31;
    if (w >= NN) return;
    int c = lane * 8;
    const float4* hp = (const float4*)&g_h1[(size_t)w * 256 + c];
    float4 h0 = hp[0], h1 = hp[1];

    // fp16 copy for the gather kernel
    __half2 q0 = __floats2half2_rn(h0.x, h0.y);
    __half2 q1 = __floats2half2_rn(h0.z, h0.w);
    __half2 q2 = __floats2half2_rn(h1.x, h1.y);
    __half2 q3 = __floats2half2_rn(h1.z, h1.w);
    __half2* qp = &g_h1h[(size_t)w * 128 + lane * 4];
    qp[0] = q0; qp[1] = q1; qp[2] = q2; qp[3] = q3;

    const float4* sp = (const float4*)&att_s[c];
    const float4* dp = (const float4*)&att_d[c];
    float4 s0 = sp[0], s1 = sp[1], d0 = dp[0], d1 = dp[1];
    float ps = h0.x * s0.x + h0.y * s0.y + h0.z * s0.z + h0.w * s0.w
             + h1.x * s1.x + h1.y * s1.y + h1.z * s1.z + h1.w * s1.w;
    float pd = h0.x * d0.x + h0.y * d0.y + h0.z * d0.z + h0.w * d0.w
             + h1.x * d1.x + h1.y * d1.y + h1.z * d1.z + h1.w * d1.w;
    #pragma unroll
    for (int o = 1; o < 8; o <<= 1) {
        ps += __shfl_xor_sync(0xffffffffu, ps, o);
        pd += __shfl_xor_sync(0xffffffffu, pd, o);
    }
    if ((lane & 7) == 0) {
        int h = lane >> 3;
        g_as1[w * 4 + h] = ps;
        g_ad1[w * 4 + h] = pd;
    }
}

// ---- fused GAT layer-1 aggregation (warp/node, fp16 gather, unroll x2) ----
__global__ void k_agg1(const float* __restrict__ b1) {
    int node = (blockIdx.x * blockDim.x + threadIdx.x) >> 5;
    int lane = threadIdx.x & 31;
    if (node >= NN) return;
    int beg = g_off[node], end = g_off[node + 1];
    int hh = lane >> 3;
    float adh = g_ad1[node * 4 + hh];

    float a0=0,a1=0,a2=0,a3=0,a4=0,a5=0,a6=0,a7=0;
    float den = 0.f;
    int i = beg;
    for (; i + 2 <= end; i += 2) {
        int s0 = g_srcid[i], s1 = g_srcid[i + 1];
        float w0 = __expf(lrelu(g_as1[s0 * 4 + hh] + adh));
        float w1 = __expf(lrelu(g_as1[s1 * 4 + hh] + adh));
        uint4 v0 = *(const uint4*)&g_h1h[(size_t)s0 * 128 + lane * 4];
        uint4 v1 = *(const uint4*)&g_h1h[(size_t)s1 * 128 + lane * 4];
        den += w0 + w1;
        float2 f;
        f = __half22float2(*(__half2*)&v0.x); a0 += f.x * w0; a1 += f.y * w0;
        f = __half22float2(*(__half2*)&v0.y); a2 += f.x * w0; a3 += f.y * w0;
        f = __half22float2(*(__half2*)&v0.z); a4 += f.x * w0; a5 += f.y * w0;
        f = __half22float2(*(__half2*)&v0.w); a6 += f.x * w0; a7 += f.y * w0;
        f = __half22float2(*(__half2*)&v1.x); a0 += f.x * w1; a1 += f.y * w1;
        f = __half22float2(*(__half2*)&v1.y); a2 += f.x * w1; a3 += f.y * w1;
        f = __half22float2(*(__half2*)&v1.z); a4 += f.x * w1; a5 += f.y * w1;
        f = __half22float2(*(__half2*)&v1.w); a6 += f.x * w1; a7 += f.y * w1;
    }
    if (i < end) {
        int s = g_srcid[i];
        float w = __expf(lrelu(g_as1[s * 4 + hh] + adh));
        den += w;
        uint4 v = *(const uint4*)&g_h1h[(size_t)s * 128 + lane * 4];
        float2 f;
        f = __half22float2(*(__half2*)&v.x); a0 += f.x * w; a1 += f.y * w;
        f = __half22float2(*(__half2*)&v.y); a2 += f.x * w; a3 += f.y * w;
        f = __half22float2(*(__half2*)&v.z); a4 += f.x * w; a5 += f.y * w;
        f = __half22float2(*(__half2*)&v.w); a6 += f.x * w; a7 += f.y * w;
    }
    float inv = 1.f / (den + 1e-16f);
    const float4* bp = (const float4*)&b1[lane * 8];
    float4 bb0 = bp[0], bb1 = bp[1];
    float o0 = a0*inv+bb0.x, o1 = a1*inv+bb0.y, o2 = a2*inv+bb0.z, o3 = a3*inv+bb0.w;
    float o4 = a4*inv+bb1.x, o5 = a5*inv+bb1.y, o6 = a6*inv+bb1.z, o7 = a7*inv+bb1.w;
    o0 = o0 > 0.f ? o0 : __expf(o0) - 1.f; o1 = o1 > 0.f ? o1 : __expf(o1) - 1.f;
    o2 = o2 > 0.f ? o2 : __expf(o2) - 1.f; o3 = o3 > 0.f ? o3 : __expf(o3) - 1.f;
    o4 = o4 > 0.f ? o4 : __expf(o4) - 1.f; o5 = o5 > 0.f ? o5 : __expf(o5) - 1.f;
    o6 = o6 > 0.f ? o6 : __expf(o6) - 1.f; o7 = o7 > 0.f ? o7 : __expf(o7) - 1.f;
    float4* op = (float4*)&g_h[(size_t)node * 256 + lane * 8];
    op[0] = make_float4(o0, o1, o2, o3);
    op[1] = make_float4(o4, o5, o6, o7);
}

// ---- attention coefficients (layer 2) + fp16 copy of h2 -------------------
__global__ void k_att2(const float* __restrict__ att_s, const float* __restrict__ att_d) {
    int w = (blockIdx.x * blockDim.x + threadIdx.x) >> 5;
    int lane = threadIdx.x & 31;
    if (w >= NN) return;
    float2 h = *(const float2*)&g_h2[(size_t)w * 64 + lane * 2];
    g_h2h[(size_t)w * 32 + lane] = __floats2half2_rn(h.x, h.y);
    float2 as = *(const float2*)&att_s[lane * 2];
    float2 ad = *(const float2*)&att_d[lane * 2];
    float ps = h.x * as.x + h.y * as.y;
    float pd = h.x * ad.x + h.y * ad.y;
    #pragma unroll
    for (int o = 16; o > 0; o >>= 1) {
        ps += __shfl_xor_sync(0xffffffffu, ps, o);
        pd += __shfl_xor_sync(0xffffffffu, pd, o);
    }
    if (lane == 0) { g_as2[w] = ps; g_ad2[w] = pd; }
}

// ---- fused GAT layer-2 aggregation + L2 normalize (fp16 gather) -----------
__global__ void k_agg2(const float* __restrict__ b2, float* __restrict__ zout) {
    int node = (blockIdx.x * blockDim.x + threadIdx.x) >> 5;
    int lane = threadIdx.x & 31;
    if (node >= NN) return;
    int beg = g_off[node], end = g_off[node + 1];
    float ad = g_ad2[node];

    float acc0 = 0.f, acc1 = 0.f, den = 0.f;
    int i = beg;
    for (; i + 2 <= end; i += 2) {
        int s0 = g_srcid[i], s1 = g_srcid[i + 1];
        float w0 = __expf(lrelu(g_as2[s0] + ad));
        float w1 = __expf(lrelu(g_as2[s1] + ad));
        float2 h0 = __half22float2(g_h2h[(size_t)s0 * 32 + lane]);
        float2 h1 = __half22float2(g_h2h[(size_t)s1 * 32 + lane]);
        den += w0 + w1;
        acc0 += h0.x * w0 + h1.x * w1;
        acc1 += h0.y * w0 + h1.y * w1;
    }
    if (i < end) {
        int s = g_srcid[i];
        float w = __expf(lrelu(g_as2[s] + ad));
        den += w;
        float2 h = __half22float2(g_h2h[(size_t)s * 32 + lane]);
        acc0 += h.x * w; acc1 += h.y * w;
    }
    float inv = 1.f / (den + 1e-16f);
    float2 bb = *(const float2*)&b2[lane * 2];
    float z0 = acc0 * inv + bb.x;
    float z1 = acc1 * inv + bb.y;
    float ss = z0 * z0 + z1 * z1;
    #pragma unroll
    for (int o = 16; o > 0; o >>= 1)
        ss += __shfl_xor_sync(0xffffffffu, ss, o);
    float invn = 1.f / fmaxf(sqrtf(ss), 1e-12f);
    float2* zp = (float2*)&zout[(size_t)node * 64 + lane * 2];
    *zp = make_float2(z0 * invn, z1 * invn);
}

// ---------------- launcher ---------------------------------------------------
extern "C" void kernel_launch(void* const* d_in, const int* in_sizes, int n_in,
                              void* d_out, int out_size) {
    float* z = (float*)d_out;                       // [NN,64]
    float* xhat = (out_size >= 9600000) ? (z + (size_t)NN * 64) : 0;

    if (out_size != 9600000)
        k_zero_out<<<(out_size + 511) / 512, 512>>>((float*)d_out, out_size);

    // real device addresses of scratch globals
    float *p_h1 = 0, *p_h = 0, *p_h2 = 0, *p_t = 0;
    cudaGetSymbolAddress((void**)&p_h1, g_h1);
    cudaGetSymbolAddress((void**)&p_h,  g_h);
    cudaGetSymbolAddress((void**)&p_h2, g_h2);
    cudaGetSymbolAddress((void**)&p_t,  g_t);

    // ---- input resolution: positional (dict order) verified by sizes ----
    static const int expect[14] = {6400000, 1600000, 32768, 256, 256, 256,
                                   16384, 64, 64, 64, 4096, 64, 8192, 128};
    bool positionalOK = (n_in == 14);
    if (positionalOK) {
        for (int i = 0; i < 14; i++) {
            int s = in_sizes[i];
            if (s != expect[i] && !(i == 1 && s == 3200000)) { positionalOK = false; break; }
        }
    }

    const float *x = 0, *W1 = 0, *W2 = 0, *dW1 = 0, *dW2 = 0, *db2 = 0;
    const float *atts1 = 0, *attd1 = 0, *b1 = 0, *atts2 = 0, *attd2 = 0, *b2 = 0, *db1 = 0;
    const int* ei = 0;

    if (positionalOK) {
        x     = (const float*)d_in[0];
        ei    = (const int*)  d_in[1];
        W1    = (const float*)d_in[2];
        atts1 = (const float*)d_in[3];
        attd1 = (const float*)d_in[4];
        b1    = (const float*)d_in[5];
        W2    = (const float*)d_in[6];
        atts2 = (const float*)d_in[7];
        attd2 = (const float*)d_in[8];
        b2    = (const float*)d_in[9];
        dW1   = (const float*)d_in[10];
        db1   = (const float*)d_in[11];
        dW2   = (const float*)d_in[12];
        db2   = (const float*)d_in[13];
    } else {
        const float* g256[3] = {0, 0, 0};
        const float* g64[4]  = {0, 0, 0, 0};
        int n256 = 0, n64 = 0;
        for (int i = 0; i < n_in; i++) {
            int s = in_sizes[i];
            const float* p = (const float*)d_in[i];
            if      (s == 6400000) x   = p;
            else if (s == 1600000 || s == 3200000) ei = (const int*)d_in[i];
            else if (s == 32768)   W1  = p;
            else if (s == 16384)   W2  = p;
            else if (s == 4096)    dW1 = p;
            else if (s == 8192)    dW2 = p;
            else if (s == 128)     db2 = p;
            else if (s == 256 && n256 < 3) g256[n256++] = p;
            else if (s == 64  && n64  < 4) g64[n64++]   = p;
        }
        bool dictLike = (n_in > 0 && in_sizes[0] == 6400000);
        atts1 = g256[dictLike ? 0 : 1];
        attd1 = g256[dictLike ? 1 : 0];
        b1    = g256[2];
        atts2 = g64[dictLike ? 0 : 1];
        attd2 = g64[dictLike ? 1 : 0];
        b2    = g64[2];
        db1   = g64[3];
        if (!x || !ei || !W1 || !W2 || !dW1 || !dW2 || !db2 || n256 < 3 || n64 < 4) {
            k_flag<<<1, 1>>>(z, 1e12f);
            return;
        }
    }

    // ---- single stream, sequential (overlap regressed in R7) ----
    k_init   <<<(NN + 255) / 256, 256>>>(ei);
    k_count  <<<(ET + 255) / 256, 256>>>(ei);
    k_scan_chunk<<<NCH, 512>>>();
    k_scan_mid  <<<1, 32>>>();
    k_scan_add  <<<NCH, 512>>>();
    k_scatter<<<(ET + 255) / 256, 256>>>(ei);

    // ---- layer 1 ----
    {
        dim3 g(2, (NN + 127) / 128);
        k_gemm128<<<g, 256>>>(x, W1, p_h1, NN, 128, 256);
    }
    k_att1<<<(NN * 32 + 255) / 256, 256>>>(atts1, attd1);
    k_agg1<<<(NN * 32 + 255) / 256, 256>>>(b1);

    // ---- layer 2 ----
    {
        dim3 g(1, (NN + 127) / 128);
        k_gemm64<<<g, 256>>>(p_h, W2, p_h2, NN, 256, 64, (const float*)0, 0);
    }
    k_att2<<<(NN * 32 + 255) / 256, 256>>>(atts2, attd2);
    k_agg2<<<(NN * 32 + 255) / 256, 256>>>(b2, z);

    // ---- decoder as two GEMMs ----
    if (xhat) {
        dim3 g1(1, (NN + 127) / 128);
        k_gemm64<<<g1, 256>>>(z, dW1, p_t, NN, 64, 64, db1, 2);     // elu(z@dW1+db1)
        dim3 g2(2, (NN + 127) / 128);
        k_gemm64<<<g2, 256>>>(p_t, dW2, xhat, NN, 64, 128, db2, 1); // @dW2+db2
    }
}

// round 10
// speedup vs baseline: 1.7343x; 1.1486x over previous
#include <cuda_runtime.h>
#include <cuda_fp16.h>
#include <cstdint>
#include <math.h>

#define NN 50000
#define EE 800000
#define ET (NN + EE)          // 850000 edges incl. self loops

// ---------------- scratch (device globals; no allocation allowed) ----------
__device__ __half  g_xh[(size_t)NN * 128];   // x in fp16
__device__ __half  g_w1h[128 * 256];         // W1 fp16
__device__ __half  g_w2h[256 * 64];          // W2 fp16
__device__ __half2 g_h1h[(size_t)NN * 128];  // h1 fp16 (gather + att src)
__device__ __half2 g_hh [(size_t)NN * 128];  // elu(gat1) fp16 (input to GEMM2)
__device__ __half2 g_h2h[(size_t)NN * 32];   // h2 fp16
__device__ float   g_t [(size_t)NN * 64];    // decoder hidden
__device__ float g_as1[NN * 4];
__device__ float g_ad1[NN * 4];
__device__ float g_as2[NN];
__device__ float g_ad2[NN];
__device__ int   g_deg[NN];
__device__ int   g_off[NN + 1];
__device__ int   g_cur[NN];
__device__ int   g_srcid[ET];
__device__ int   g_ei64;

__device__ __forceinline__ float lrelu(float v) { return v >= 0.f ? v : 0.2f * v; }

__device__ __forceinline__ int load_edge(const int* __restrict__ ei, int j) {
    return g_ei64 ? ei[(size_t)j * 2] : ei[j];   // little-endian low word
}

__global__ void k_flag(float* __restrict__ z, float v) { z[0] = v; }

__global__ void k_zero_out(float* __restrict__ o, int n) {
    int i = blockIdx.x * blockDim.x + threadIdx.x;
    if (i < n) o[i] = 0.f;
}

// ------- init: zero degrees + att accumulators + dtype detect --------------
__global__ void k_init(const int* __restrict__ ei) {
    int i = blockIdx.x * blockDim.x + threadIdx.x;
    if (i < NN) {
        g_deg[i] = 0;
        g_as2[i] = 0.f; g_ad2[i] = 0.f;
        #pragma unroll
        for (int h = 0; h < 4; h++) { g_as1[i * 4 + h] = 0.f; g_ad1[i * 4 + h] = 0.f; }
    }
    if (i == 0) {
        int odd_nz = 0, even_nz = 0;
        for (int j = 0; j < 256; j += 2) {
            if (ei[j]     != 0) even_nz++;
            if (ei[j + 1] != 0) odd_nz++;
        }
        g_ei64 = (odd_nz == 0 && even_nz > 0) ? 1 : 0;
    }
}

// ------- fp32 -> fp16 conversion of x, W1, W2 (pairwise) --------------------
#define XPAIRS 3200000
#define W1PAIRS 16384
#define W2PAIRS 8192
__global__ void k_cvt(const float* __restrict__ x, const float* __restrict__ W1,
                      const float* __restrict__ W2) {
    int p = blockIdx.x * blockDim.x + threadIdx.x;
    if (p < XPAIRS) {
        float2 v = *(const float2*)&x[(size_t)p * 2];
        *(__half2*)&g_xh[(size_t)p * 2] = __floats2half2_rn(v.x, v.y);
    } else if (p < XPAIRS + W1PAIRS) {
        int q = p - XPAIRS;
        float2 v = *(const float2*)&W1[(size_t)q * 2];
        *(__half2*)&g_w1h[(size_t)q * 2] = __floats2half2_rn(v.x, v.y);
    } else if (p < XPAIRS + W1PAIRS + W2PAIRS) {
        int q = p - XPAIRS - W1PAIRS;
        float2 v = *(const float2*)&W2[(size_t)q * 2];
        *(__half2*)&g_w2h[(size_t)q * 2] = __floats2half2_rn(v.x, v.y);
    }
}

// ---------------- CSR build -------------------------------------------------
__global__ void k_count(const int* __restrict__ ei) {
    int e = blockIdx.x * blockDim.x + threadIdx.x;
    if (e >= ET) return;
    int dst = (e < EE) ? load_edge(ei, EE + e) : (e - EE);
    if ((unsigned)dst < (unsigned)NN) atomicAdd(&g_deg[dst], 1);
}

// single-block scan: 1024 threads x 49 elements
__global__ void k_scan1() {
    const int PER = 49;
    __shared__ int ws[32];
    int tid = threadIdx.x;
    int base = tid * PER;
    int sum = 0;
    for (int j = 0; j < PER; j++) { int idx = base + j; if (idx < NN) sum += g_deg[idx]; }
    int lane = tid & 31, w = tid >> 5;
    int v = sum;
    #pragma unroll
    for (int o = 1; o < 32; o <<= 1) {
        int t = __shfl_up_sync(0xffffffffu, v, o);
        if (lane >= o) v += t;
    }
    if (lane == 31) ws[w] = v;
    __syncthreads();
    if (w == 0) {
        int xv = ws[lane];
        #pragma unroll
        for (int o = 1; o < 32; o <<= 1) {
            int t = __shfl_up_sync(0xffffffffu, xv, o);
            if (lane >= o) xv += t;
        }
        ws[lane] = xv;
    }
    __syncthreads();
    int run = (v - sum) + (w > 0 ? ws[w - 1] : 0);
    for (int j = 0; j < PER; j++) {
        int idx = base + j;
        if (idx < NN) {
            int d = g_deg[idx];
            g_off[idx] = run; g_cur[idx] = run;
            run += d;
        }
    }
    if (tid == 0) g_off[NN] = ET;
}

__global__ void k_scatter(const int* __restrict__ ei) {
    int e = blockIdx.x * blockDim.x + threadIdx.x;
    if (e >= ET) return;
    int s, d;
    if (e < EE) { s = load_edge(ei, e); d = load_edge(ei, EE + e); }
    else        { s = d = e - EE; }
    if ((unsigned)d >= (unsigned)NN || (unsigned)s >= (unsigned)NN) return;
    int p = atomicAdd(&g_cur[d], 1);
    if ((unsigned)p < (unsigned)ET) g_srcid[p] = s;
}

// ------- fp16 tensor-core GEMM + fused attention-coefficient epilogue ------
// C_h[M,N](fp16) = A(fp16)[M,K] @ B(fp16)[K,N]; also as/ad[row] += h.att dots.
// BM=128, BN=64 (== head width), BK=32, 256 threads (8 warps: 4m x 2n).
template<int K, int HS>
__global__ void k_hgemm_att(const __half* __restrict__ A, const __half* __restrict__ B,
                            __half2* __restrict__ Ch, int M, int N,
                            const float* __restrict__ att_s, const float* __restrict__ att_d,
                            float* __restrict__ as_out, float* __restrict__ ad_out) {
    __shared__ __half As[128][40];
    __shared__ __half Bs[64][42];
    int bm = blockIdx.y * 128, bn = blockIdx.x * 64;
    int tid = threadIdx.x, lane = tid & 31, wid = tid >> 5;
    int wm = wid & 3, wn = wid >> 2;
    int g = lane >> 2, tc = lane & 3;
    float acc[2][4][4] = {};
    for (int k0 = 0; k0 < K; k0 += 32) {
        #pragma unroll
        for (int t = 0; t < 2; t++) {
            int i = tid + t * 256;
            int r = i >> 2, seg = i & 3;
            int row = bm + r;
            uint4 v = make_uint4(0u, 0u, 0u, 0u);
            if (row < M) v = *(const uint4*)&A[(size_t)row * K + k0 + seg * 8];
            *(uint4*)&As[r][seg * 8] = v;
        }
        #pragma unroll
        for (int t = 0; t < 4; t++) {
            int i = tid + t * 256;
            int kk = i >> 5, nn = (i & 31) * 2;
            __half2 v = *(const __half2*)&B[(size_t)(k0 + kk) * N + bn + nn];
            Bs[nn][kk]     = __low2half(v);
            Bs[nn + 1][kk] = __high2half(v);
        }
        __syncthreads();
        #pragma unroll
        for (int ks = 0; ks < 2; ks++) {
            int kb = ks * 16;
            uint32_t af[2][4], bf[4][2];
            #pragma unroll
            for (int mt = 0; mt < 2; mt++) {
                int r = wm * 32 + mt * 16 + g;
                af[mt][0] = *(const uint32_t*)&As[r][kb + tc * 2];
                af[mt][1] = *(const uint32_t*)&As[r + 8][kb + tc * 2];
                af[mt][2] = *(const uint32_t*)&As[r][kb + tc * 2 + 8];
                af[mt][3] = *(const uint32_t*)&As[r + 8][kb + tc * 2 + 8];
            }
            #pragma unroll
            for (int nt = 0; nt < 4; nt++) {
                int n = wn * 32 + nt * 8 + g;
                bf[nt][0] = *(const uint32_t*)&Bs[n][kb + tc * 2];
                bf[nt][1] = *(const uint32_t*)&Bs[n][kb + tc * 2 + 8];
            }
            #pragma unroll
            for (int mt = 0; mt < 2; mt++)
                #pragma unroll
                for (int nt = 0; nt < 4; nt++)
                    asm volatile(
                        "mma.sync.aligned.m16n8k16.row.col.f32.f16.f16.f32 "
                        "{%0,%1,%2,%3},{%4,%5,%6,%7},{%8,%9},{%0,%1,%2,%3};"
                        : "+f"(acc[mt][nt][0]), "+f"(acc[mt][nt][1]),
                          "+f"(acc[mt][nt][2]), "+f"(acc[mt][nt][3])
                        : "r"(af[mt][0]), "r"(af[mt][1]), "r"(af[mt][2]), "r"(af[mt][3]),
                          "r"(bf[nt][0]), "r"(bf[nt][1]));
        }
        __syncthreads();
    }
    // epilogue: fp16 store + fused attention dot products
    int hh = bn >> 6;
    int N2 = N >> 1;
    #pragma unroll
    for (int mt = 0; mt < 2; mt++) {
        #pragma unroll
        for (int hf = 0; hf < 2; hf++) {
            int row = bm + wm * 32 + mt * 16 + g + hf * 8;
            float ps = 0.f, pd = 0.f;
            if (row < M) {
                #pragma unroll
                for (int nt = 0; nt < 4; nt++) {
                    int cl = wn * 32 + nt * 8 + tc * 2;
                    float v0 = acc[mt][nt][hf * 2 + 0];
                    float v1 = acc[mt][nt][hf * 2 + 1];
                    Ch[(size_t)row * N2 + ((bn + cl) >> 1)] = __floats2half2_rn(v0, v1);
                    ps += v0 * att_s[bn + cl] + v1 * att_s[bn + cl + 1];
                    pd += v0 * att_d[bn + cl] + v1 * att_d[bn + cl + 1];
                }
            }
            ps += __shfl_xor_sync(0xffffffffu, ps, 1);
            pd += __shfl_xor_sync(0xffffffffu, pd, 1);
            ps += __shfl_xor_sync(0xffffffffu, ps, 2);
            pd += __shfl_xor_sync(0xffffffffu, pd, 2);
            if (tc == 0 && row < M) {
                atomicAdd(&as_out[row * HS + hh], ps);
                atomicAdd(&ad_out[row * HS + hh], pd);
            }
        }
    }
}

// ------- GEMM fp32: BM=128, BN=64, BK=16; epi: 1 bias, 2 bias+elu (decoder) -
__global__ void k_gemm64(const float* __restrict__ A, const float* __restrict__ B,
                         float* __restrict__ C, int M, int K, int Nc,
                         const float* __restrict__ bias, int epi) {
    __shared__ float As[16][132];
    __shared__ float Bs[16][68];
    int bm = blockIdx.y * 128, bn = blockIdx.x * 64;
    int tid = threadIdx.x;
    int tx = tid & 15, ty = tid >> 4;
    float acc[8][4] = {};
    for (int k0 = 0; k0 < K; k0 += 16) {
        #pragma unroll
        for (int i = tid; i < 128 * 16; i += 256) {
            int r = i >> 4, c = i & 15;
            int gr = bm + r;
            As[c][r] = (gr < M) ? A[(size_t)gr * K + k0 + c] : 0.f;
        }
        #pragma unroll
        for (int i = tid; i < 16 * 64; i += 256) {
            int r = i >> 6, c = i & 63;
            Bs[r][c] = B[(size_t)(k0 + r) * Nc + bn + c];
        }
        __syncthreads();
        #pragma unroll
        for (int k = 0; k < 16; k++) {
            float a[8], b[4];
            #pragma unroll
            for (int u = 0; u < 8; u++) a[u] = As[k][ty * 8 + u];
            #pragma unroll
            for (int v = 0; v < 4; v++) b[v] = Bs[k][tx * 4 + v];
            #pragma unroll
            for (int u = 0; u < 8; u++)
                #pragma unroll
                for (int v = 0; v < 4; v++) acc[u][v] += a[u] * b[v];
        }
        __syncthreads();
    }
    float bb[4] = {0.f, 0.f, 0.f, 0.f};
    if (epi) {
        #pragma unroll
        for (int v = 0; v < 4; v++) bb[v] = bias[bn + tx * 4 + v];
    }
    #pragma unroll
    for (int u = 0; u < 8; u++) {
        int gr = bm + ty * 8 + u;
        if (gr < M) {
            float o[4];
            #pragma unroll
            for (int v = 0; v < 4; v++) {
                float t = acc[u][v] + bb[v];
                if (epi == 2) t = t > 0.f ? t : __expf(t) - 1.f;
                o[v] = t;
            }
            *(float4*)&C[(size_t)gr * Nc + bn + tx * 4] = make_float4(o[0], o[1], o[2], o[3]);
        }
    }
}

// ---- fused GAT layer-1 aggregation (warp/node, fp16 gather, fp16 out) -----
__global__ void k_agg1(const float* __restrict__ b1) {
    int node = (blockIdx.x * blockDim.x + threadIdx.x) >> 5;
    int lane = threadIdx.x & 31;
    if (node >= NN) return;
    int beg = g_off[node], end = g_off[node + 1];
    int hh = lane >> 3;
    float adh = g_ad1[node * 4 + hh];

    float a0=0,a1=0,a2=0,a3=0,a4=0,a5=0,a6=0,a7=0;
    float den = 0.f;
    int i = beg;
    for (; i + 2 <= end; i += 2) {
        int s0 = g_srcid[i], s1 = g_srcid[i + 1];
        float w0 = __expf(lrelu(g_as1[s0 * 4 + hh] + adh));
        float w1 = __expf(lrelu(g_as1[s1 * 4 + hh] + adh));
        uint4 v0 = *(const uint4*)&g_h1h[(size_t)s0 * 128 + lane * 4];
        uint4 v1 = *(const uint4*)&g_h1h[(size_t)s1 * 128 + lane * 4];
        den += w0 + w1;
        float2 f;
        f = __half22float2(*(__half2*)&v0.x); a0 += f.x * w0; a1 += f.y * w0;
        f = __half22float2(*(__half2*)&v0.y); a2 += f.x * w0; a3 += f.y * w0;
        f = __half22float2(*(__half2*)&v0.z); a4 += f.x * w0; a5 += f.y * w0;
        f = __half22float2(*(__half2*)&v0.w); a6 += f.x * w0; a7 += f.y * w0;
        f = __half22float2(*(__half2*)&v1.x); a0 += f.x * w1; a1 += f.y * w1;
        f = __half22float2(*(__half2*)&v1.y); a2 += f.x * w1; a3 += f.y * w1;
        f = __half22float2(*(__half2*)&v1.z); a4 += f.x * w1; a5 += f.y * w1;
        f = __half22float2(*(__half2*)&v1.w); a6 += f.x * w1; a7 += f.y * w1;
    }
    if (i < end) {
        int s = g_srcid[i];
        float w = __expf(lrelu(g_as1[s * 4 + hh] + adh));
        den += w;
        uint4 v = *(const uint4*)&g_h1h[(size_t)s * 128 + lane * 4];
        float2 f;
        f = __half22float2(*(__half2*)&v.x); a0 += f.x * w; a1 += f.y * w;
        f = __half22float2(*(__half2*)&v.y); a2 += f.x * w; a3 += f.y * w;
        f = __half22float2(*(__half2*)&v.z); a4 += f.x * w; a5 += f.y * w;
        f = __half22float2(*(__half2*)&v.w); a6 += f.x * w; a7 += f.y * w;
    }
    float inv = 1.f / (den + 1e-16f);
    const float4* bp = (const float4*)&b1[lane * 8];
    float4 bb0 = bp[0], bb1 = bp[1];
    float o0 = a0*inv+bb0.x, o1 = a1*inv+bb0.y, o2 = a2*inv+bb0.z, o3 = a3*inv+bb0.w;
    float o4 = a4*inv+bb1.x, o5 = a5*inv+bb1.y, o6 = a6*inv+bb1.z, o7 = a7*inv+bb1.w;
    o0 = o0 > 0.f ? o0 : __expf(o0) - 1.f; o1 = o1 > 0.f ? o1 : __expf(o1) - 1.f;
    o2 = o2 > 0.f ? o2 : __expf(o2) - 1.f; o3 = o3 > 0.f ? o3 : __expf(o3) - 1.f;
    o4 = o4 > 0.f ? o4 : __expf(o4) - 1.f; o5 = o5 > 0.f ? o5 : __expf(o5) - 1.f;
    o6 = o6 > 0.f ? o6 : __expf(o6) - 1.f; o7 = o7 > 0.f ? o7 : __expf(o7) - 1.f;
    __half2* op = &g_hh[(size_t)node * 128 + lane * 4];
    op[0] = __floats2half2_rn(o0, o1);
    op[1] = __floats2half2_rn(o2, o3);
    op[2] = __floats2half2_rn(o4, o5);
    op[3] = __floats2half2_rn(o6, o7);
}

// ---- fused GAT layer-2 aggregation + L2 normalize (fp16 gather) -----------
__global__ void k_agg2(const float* __restrict__ b2, float* __restrict__ zout) {
    int node = (blockIdx.x * blockDim.x + threadIdx.x) >> 5;
    int lane = threadIdx.x & 31;
    if (node >= NN) return;
    int beg = g_off[node], end = g_off[node + 1];
    float ad = g_ad2[node];

    float acc0 = 0.f, acc1 = 0.f, den = 0.f;
    int i = beg;
    for (; i + 2 <= end; i += 2) {
        int s0 = g_srcid[i], s1 = g_srcid[i + 1];
        float w0 = __expf(lrelu(g_as2[s0] + ad));
        float w1 = __expf(lrelu(g_as2[s1] + ad));
        float2 h0 = __half22float2(g_h2h[(size_t)s0 * 32 + lane]);
        float2 h1 = __half22float2(g_h2h[(size_t)s1 * 32 + lane]);
        den += w0 + w1;
        acc0 += h0.x * w0 + h1.x * w1;
        acc1 += h0.y * w0 + h1.y * w1;
    }
    if (i < end) {
        int s = g_srcid[i];
        float w = __expf(lrelu(g_as2[s] + ad));
        den += w;
        float2 h = __half22float2(g_h2h[(size_t)s * 32 + lane]);
        acc0 += h.x * w; acc1 += h.y * w;
    }
    float inv = 1.f / (den + 1e-16f);
    float2 bb = *(const float2*)&b2[lane * 2];
    float z0 = acc0 * inv + bb.x;
    float z1 = acc1 * inv + bb.y;
    float ss = z0 * z0 + z1 * z1;
    #pragma unroll
    for (int o = 16; o > 0; o >>= 1)
        ss += __shfl_xor_sync(0xffffffffu, ss, o);
    float invn = 1.f / fmaxf(sqrtf(ss), 1e-12f);
    float2* zp = (float2*)&zout[(size_t)node * 64 + lane * 2];
    *zp = make_float2(z0 * invn, z1 * invn);
}

// ---------------- launcher ---------------------------------------------------
extern "C" void kernel_launch(void* const* d_in, const int* in_sizes, int n_in,
                              void* d_out, int out_size) {
    float* z = (float*)d_out;                       // [NN,64]
    float* xhat = (out_size >= 9600000) ? (z + (size_t)NN * 64) : 0;

    if (out_size != 9600000)
        k_zero_out<<<(out_size + 511) / 512, 512>>>((float*)d_out, out_size);

    // device addresses of scratch globals (host-passable)
    void *p_xh, *p_w1h, *p_w2h, *p_h1h, *p_hh, *p_h2h, *p_t;
    void *p_as1, *p_ad1, *p_as2, *p_ad2;
    cudaGetSymbolAddress(&p_xh,  g_xh);
    cudaGetSymbolAddress(&p_w1h, g_w1h);
    cudaGetSymbolAddress(&p_w2h, g_w2h);
    cudaGetSymbolAddress(&p_h1h, g_h1h);
    cudaGetSymbolAddress(&p_hh,  g_hh);
    cudaGetSymbolAddress(&p_h2h, g_h2h);
    cudaGetSymbolAddress(&p_t,   g_t);
    cudaGetSymbolAddress(&p_as1, g_as1);
    cudaGetSymbolAddress(&p_ad1, g_ad1);
    cudaGetSymbolAddress(&p_as2, g_as2);
    cudaGetSymbolAddress(&p_ad2, g_ad2);

    // ---- input resolution: positional (dict order) verified by sizes ----
    static const int expect[14] = {6400000, 1600000, 32768, 256, 256, 256,
                                   16384, 64, 64, 64, 4096, 64, 8192, 128};
    bool positionalOK = (n_in == 14);
    if (positionalOK) {
        for (int i = 0; i < 14; i++) {
            int s = in_sizes[i];
            if (s != expect[i] && !(i == 1 && s == 3200000)) { positionalOK = false; break; }
        }
    }

    const float *x = 0, *W1 = 0, *W2 = 0, *dW1 = 0, *dW2 = 0, *db2 = 0;
    const float *atts1 = 0, *attd1 = 0, *b1 = 0, *atts2 = 0, *attd2 = 0, *b2 = 0, *db1 = 0;
    const int* ei = 0;

    if (positionalOK) {
        x     = (const float*)d_in[0];
        ei    = (const int*)  d_in[1];
        W1    = (const float*)d_in[2];
        atts1 = (const float*)d_in[3];
        attd1 = (const float*)d_in[4];
        b1    = (const float*)d_in[5];
        W2    = (const float*)d_in[6];
        atts2 = (const float*)d_in[7];
        attd2 = (const float*)d_in[8];
        b2    = (const float*)d_in[9];
        dW1   = (const float*)d_in[10];
        db1   = (const float*)d_in[11];
        dW2   = (const float*)d_in[12];
        db2   = (const float*)d_in[13];
    } else {
        const float* g256[3] = {0, 0, 0};
        const float* g64[4]  = {0, 0, 0, 0};
        int n256 = 0, n64 = 0;
        for (int i = 0; i < n_in; i++) {
            int s = in_sizes[i];
            const float* p = (const float*)d_in[i];
            if      (s == 6400000) x   = p;
            else if (s == 1600000 || s == 3200000) ei = (const int*)d_in[i];
            else if (s == 32768)   W1  = p;
            else if (s == 16384)   W2  = p;
            else if (s == 4096)    dW1 = p;
            else if (s == 8192)    dW2 = p;
            else if (s == 128)     db2 = p;
            else if (s == 256 && n256 < 3) g256[n256++] = p;
            else if (s == 64  && n64  < 4) g64[n64++]   = p;
        }
        bool dictLike = (n_in > 0 && in_sizes[0] == 6400000);
        atts1 = g256[dictLike ? 0 : 1];
        attd1 = g256[dictLike ? 1 : 0];
        b1    = g256[2];
        atts2 = g64[dictLike ? 0 : 1];
        attd2 = g64[dictLike ? 1 : 0];
        b2    = g64[2];
        db1   = g64[3];
        if (!x || !ei || !W1 || !W2 || !dW1 || !dW2 || !db2 || n256 < 3 || n64 < 4) {
            k_flag<<<1, 1>>>(z, 1e12f);
            return;
        }
    }

    // ---- init + CSR ----
    k_init <<<(NN + 255) / 256, 256>>>(ei);
    k_count<<<(ET + 255) / 256, 256>>>(ei);
    k_scan1<<<1, 1024>>>();
    k_scatter<<<(ET + 255) / 256, 256>>>(ei);

    // ---- fp16 conversion ----
    k_cvt<<<(XPAIRS + W1PAIRS + W2PAIRS + 255) / 256, 256>>>(x, W1, W2);

    // ---- layer 1: tensor-core GEMM + fused att1 ----
    {
        dim3 g(4, (NN + 127) / 128);
        k_hgemm_att<128, 4><<<g, 256>>>((const __half*)p_xh, (const __half*)p_w1h,
                                        (__half2*)p_h1h, NN, 256,
                                        atts1, attd1, (float*)p_as1, (float*)p_ad1);
    }
    k_agg1<<<(NN * 32 + 255) / 256, 256>>>(b1);

    // ---- layer 2: tensor-core GEMM + fused att2 ----
    {
        dim3 g(1, (NN + 127) / 128);
        k_hgemm_att<256, 1><<<g, 256>>>((const __half*)p_hh, (const __half*)p_w2h,
                                        (__half2*)p_h2h, NN, 64,
                                        atts2, attd2, (float*)p_as2, (float*)p_ad2);
    }
    k_agg2<<<(NN * 32 + 255) / 256, 256>>>(b2, z);

    // ---- decoder as two fp32 GEMMs ----
    if (xhat) {
        dim3 g1(1, (NN + 127) / 128);
        k_gemm64<<<g1, 256>>>(z, dW1, (float*)p_t, NN, 64, 64, db1, 2);
        dim3 g2(2, (NN + 127) / 128);
        k_gemm64<<<g2, 256>>>((float*)p_t, dW2, xhat, NN, 64, 128, db2, 1);
    }
}